// round 2
// baseline (speedup 1.0000x reference)
#include <cuda_runtime.h>
#include <cuda_bf16.h>

#define DF 1024
#define NH 16
#define DH 64
#define BB 2
#define SS 2048
#define MROWS (BB*SS)

// Scratch: Q/K/V projections + attention output (pre output-proj).
__device__ float g_Qf[MROWS * DF];
__device__ float g_Kf[MROWS * DF];
__device__ float g_Vf[MROWS * DF];
__device__ float g_Xc[MROWS * DF];

// ---------------------------------------------------------------------------
// GEMM: C[M,N] = A[M,K] @ W[N,K]^T + bias[N]
// M=4096, N=K=1024. Both A and W are K-major (row-major along K) -> NT GEMM.
// 64x64 tile, BK=16, 256 threads, 4x4 micro-tile per thread. fp32 FFMA.
// ---------------------------------------------------------------------------
__global__ __launch_bounds__(256) void gemm_nt_bias(
    const float* __restrict__ A, const float* __restrict__ W,
    const float* __restrict__ bias, float* __restrict__ C)
{
    const int BM = 64, BN = 64, BK = 16;
    __shared__ float As[BK][BM + 4];
    __shared__ float Ws[BK][BN + 4];

    const int tid = threadIdx.x;
    const int tx = tid & 15;        // 0..15  (N direction)
    const int ty = tid >> 4;        // 0..15  (M direction)
    const int m0 = blockIdx.y * BM;
    const int n0 = blockIdx.x * BN;

    // cooperative load indices: each thread loads one float4 of A and W
    const int lr = tid >> 2;            // 0..63 row within tile
    const int lc = (tid & 3) << 2;      // 0,4,8,12 k within tile

    float acc[4][4] = {};

    for (int k0 = 0; k0 < DF; k0 += BK) {
        float4 av = *reinterpret_cast<const float4*>(A + (size_t)(m0 + lr) * DF + k0 + lc);
        float4 wv = *reinterpret_cast<const float4*>(W + (size_t)(n0 + lr) * DF + k0 + lc);
        As[lc + 0][lr] = av.x; As[lc + 1][lr] = av.y;
        As[lc + 2][lr] = av.z; As[lc + 3][lr] = av.w;
        Ws[lc + 0][lr] = wv.x; Ws[lc + 1][lr] = wv.y;
        Ws[lc + 2][lr] = wv.z; Ws[lc + 3][lr] = wv.w;
        __syncthreads();

        #pragma unroll
        for (int kk = 0; kk < BK; kk++) {
            float4 a4 = *reinterpret_cast<const float4*>(&As[kk][ty << 2]);
            float4 w4 = *reinterpret_cast<const float4*>(&Ws[kk][tx << 2]);
            float a[4] = {a4.x, a4.y, a4.z, a4.w};
            float w[4] = {w4.x, w4.y, w4.z, w4.w};
            #pragma unroll
            for (int i = 0; i < 4; i++)
                #pragma unroll
                for (int j = 0; j < 4; j++)
                    acc[i][j] += a[i] * w[j];
        }
        __syncthreads();
    }

    #pragma unroll
    for (int i = 0; i < 4; i++) {
        int m = m0 + (ty << 2) + i;
        #pragma unroll
        for (int j = 0; j < 4; j++) {
            int n = n0 + (tx << 2) + j;
            C[(size_t)m * DF + n] = acc[i][j] + bias[n];
        }
    }
}

// ---------------------------------------------------------------------------
// Flash-style attention. One thread per query row; block = 256 queries for
// one (batch, head). Online softmax with deferred rescale (rescale o[] only
// when the running max actually increases -> o-update is 1 FMA/elem).
// Scores match the reference exactly: masked keys get score = -1e9.
// Scale = 1/sqrt(D_FEAT) = 1/32 (reference quirk: d_feat, not d_head).
// ---------------------------------------------------------------------------
__global__ __launch_bounds__(256) void attn_kernel(
    const float* __restrict__ Qf, const float* __restrict__ Kf,
    const float* __restrict__ Vf, const int* __restrict__ mask,
    float* __restrict__ Xc)
{
    const int b = blockIdx.z;
    const int h = blockIdx.y;
    const int q = blockIdx.x * 256 + threadIdx.x;

    __shared__ float Ks[64][64];
    __shared__ float Vs[64][64];
    __shared__ float mk[64];

    float qv[DH], o[DH];
    const float* qrow = Qf + ((size_t)(b * SS + q)) * DF + h * DH;
    #pragma unroll
    for (int i = 0; i < DH / 4; i++) {
        float4 v = reinterpret_cast<const float4*>(qrow)[i];
        qv[4*i] = v.x; qv[4*i+1] = v.y; qv[4*i+2] = v.z; qv[4*i+3] = v.w;
    }
    #pragma unroll
    for (int i = 0; i < DH; i++) o[i] = 0.f;

    float m = -1e30f, l = 0.f;

    const int lr = threadIdx.x >> 2;          // 0..63
    const int lc = (threadIdx.x & 3) << 4;    // 0,16,32,48

    for (int kt = 0; kt < SS; kt += 64) {
        __syncthreads();
        const float* kr = Kf + ((size_t)(b * SS + kt + lr)) * DF + h * DH + lc;
        const float* vr = Vf + ((size_t)(b * SS + kt + lr)) * DF + h * DH + lc;
        #pragma unroll
        for (int j = 0; j < 16; j += 4) {
            float4 kv = *reinterpret_cast<const float4*>(kr + j);
            float4 vv = *reinterpret_cast<const float4*>(vr + j);
            *reinterpret_cast<float4*>(&Ks[lr][lc + j]) = kv;
            *reinterpret_cast<float4*>(&Vs[lr][lc + j]) = vv;
        }
        if (threadIdx.x < 64)
            mk[threadIdx.x] = (mask[b * SS + kt + threadIdx.x] == 0) ? 1.f : 0.f;
        __syncthreads();

        for (int k = 0; k < 64; k++) {
            // q . K[k]  (broadcast LDS.128, 4 partial accumulators)
            float d0 = 0.f, d1 = 0.f, d2 = 0.f, d3 = 0.f;
            const float4* krow4 = reinterpret_cast<const float4*>(&Ks[k][0]);
            #pragma unroll
            for (int i = 0; i < 16; i++) {
                float4 kv = krow4[i];
                d0 += qv[4*i]   * kv.x;
                d1 += qv[4*i+1] * kv.y;
                d2 += qv[4*i+2] * kv.z;
                d3 += qv[4*i+3] * kv.w;
            }
            float s = ((d0 + d1) + (d2 + d3)) * 0.03125f;
            if (mk[k] != 0.f) s = -1e9f;

            if (s > m) {                       // deferred rescale (rare)
                float c = __expf(m - s);
                l *= c;
                #pragma unroll
                for (int i = 0; i < DH; i++) o[i] *= c;
                m = s;
            }
            float p = __expf(s - m);
            l += p;

            const float4* vrow4 = reinterpret_cast<const float4*>(&Vs[k][0]);
            #pragma unroll
            for (int i = 0; i < 16; i++) {
                float4 vv = vrow4[i];
                o[4*i]   += p * vv.x;
                o[4*i+1] += p * vv.y;
                o[4*i+2] += p * vv.z;
                o[4*i+3] += p * vv.w;
            }
        }
    }

    float inv = 1.f / l;
    float* xr = Xc + ((size_t)(b * SS + q)) * DF + h * DH;
    #pragma unroll
    for (int i = 0; i < DH / 4; i++) {
        float4 v = {o[4*i] * inv, o[4*i+1] * inv, o[4*i+2] * inv, o[4*i+3] * inv};
        reinterpret_cast<float4*>(xr)[i] = v;
    }
}

// ---------------------------------------------------------------------------
// launch
// ---------------------------------------------------------------------------
extern "C" void kernel_launch(void* const* d_in, const int* in_sizes, int n_in,
                              void* d_out, int out_size)
{
    const float* Q    = (const float*)d_in[0];
    const float* K    = (const float*)d_in[1];
    const float* V    = (const float*)d_in[2];
    const int*   mask = (const int*)  d_in[3];
    const float* Wq   = (const float*)d_in[4];
    const float* bq   = (const float*)d_in[5];
    const float* Wk   = (const float*)d_in[6];
    const float* bk   = (const float*)d_in[7];
    const float* Wv   = (const float*)d_in[8];
    const float* bv   = (const float*)d_in[9];
    const float* Wo   = (const float*)d_in[10];
    const float* bo   = (const float*)d_in[11];
    float* out = (float*)d_out;

    float *Qf, *Kf, *Vf, *Xc;
    cudaGetSymbolAddress((void**)&Qf, g_Qf);
    cudaGetSymbolAddress((void**)&Kf, g_Kf);
    cudaGetSymbolAddress((void**)&Vf, g_Vf);
    cudaGetSymbolAddress((void**)&Xc, g_Xc);

    dim3 ggrid(DF / 64, MROWS / 64);   // (16, 64)
    dim3 gblk(256);

    gemm_nt_bias<<<ggrid, gblk>>>(Q, Wq, bq, Qf);
    gemm_nt_bias<<<ggrid, gblk>>>(K, Wk, bk, Kf);
    gemm_nt_bias<<<ggrid, gblk>>>(V, Wv, bv, Vf);

    attn_kernel<<<dim3(SS / 256, NH, BB), 256>>>(Qf, Kf, Vf, mask, Xc);

    gemm_nt_bias<<<ggrid, gblk>>>(Xc, Wo, bo, out);
}

// round 3
// speedup vs baseline: 1.0012x; 1.0012x over previous
#include <cuda_runtime.h>
#include <cuda_bf16.h>

#define DF 1024
#define NH 16
#define DH 64
#define BB 2
#define SS 2048
#define MROWS (BB*SS)

// Scratch: Q/K/V projections + attention output (pre output-proj).
__device__ float g_Qf[MROWS * DF];
__device__ float g_Kf[MROWS * DF];
__device__ float g_Vf[MROWS * DF];
__device__ float g_Xc[MROWS * DF];

// ---------------------------------------------------------------------------
// GEMM: C[M,N] = A[M,K] @ W[N,K]^T + bias[N]
// M=4096, N=K=1024. Both A and W are K-major (row-major along K) -> NT GEMM.
// 64x64 tile, BK=16, 256 threads, 4x4 micro-tile per thread. fp32 FFMA.
// ---------------------------------------------------------------------------
__global__ __launch_bounds__(256) void gemm_nt_bias(
    const float* __restrict__ A, const float* __restrict__ W,
    const float* __restrict__ bias, float* __restrict__ C)
{
    const int BM = 64, BN = 64, BK = 16;
    __shared__ float As[BK][BM + 4];
    __shared__ float Ws[BK][BN + 4];

    const int tid = threadIdx.x;
    const int tx = tid & 15;        // 0..15  (N direction)
    const int ty = tid >> 4;        // 0..15  (M direction)
    const int m0 = blockIdx.y * BM;
    const int n0 = blockIdx.x * BN;

    // cooperative load indices: each thread loads one float4 of A and W
    const int lr = tid >> 2;            // 0..63 row within tile
    const int lc = (tid & 3) << 2;      // 0,4,8,12 k within tile

    float acc[4][4] = {};

    for (int k0 = 0; k0 < DF; k0 += BK) {
        float4 av = *reinterpret_cast<const float4*>(A + (size_t)(m0 + lr) * DF + k0 + lc);
        float4 wv = *reinterpret_cast<const float4*>(W + (size_t)(n0 + lr) * DF + k0 + lc);
        As[lc + 0][lr] = av.x; As[lc + 1][lr] = av.y;
        As[lc + 2][lr] = av.z; As[lc + 3][lr] = av.w;
        Ws[lc + 0][lr] = wv.x; Ws[lc + 1][lr] = wv.y;
        Ws[lc + 2][lr] = wv.z; Ws[lc + 3][lr] = wv.w;
        __syncthreads();

        #pragma unroll
        for (int kk = 0; kk < BK; kk++) {
            float4 a4 = *reinterpret_cast<const float4*>(&As[kk][ty << 2]);
            float4 w4 = *reinterpret_cast<const float4*>(&Ws[kk][tx << 2]);
            float a[4] = {a4.x, a4.y, a4.z, a4.w};
            float w[4] = {w4.x, w4.y, w4.z, w4.w};
            #pragma unroll
            for (int i = 0; i < 4; i++)
                #pragma unroll
                for (int j = 0; j < 4; j++)
                    acc[i][j] += a[i] * w[j];
        }
        __syncthreads();
    }

    #pragma unroll
    for (int i = 0; i < 4; i++) {
        int m = m0 + (ty << 2) + i;
        #pragma unroll
        for (int j = 0; j < 4; j++) {
            int n = n0 + (tx << 2) + j;
            C[(size_t)m * DF + n] = acc[i][j] + bias[n];
        }
    }
}

// ---------------------------------------------------------------------------
// Flash-style attention. One thread per query row; block = 256 queries for
// one (batch, head). Online softmax with deferred rescale (rescale o[] only
// when the running max actually increases -> o-update is 1 FMA/elem).
// Scores match the reference exactly: masked keys get score = -1e9.
// Scale = 1/sqrt(D_FEAT) = 1/32 (reference quirk: d_feat, not d_head).
// ---------------------------------------------------------------------------
__global__ __launch_bounds__(256) void attn_kernel(
    const float* __restrict__ Qf, const float* __restrict__ Kf,
    const float* __restrict__ Vf, const int* __restrict__ mask,
    float* __restrict__ Xc)
{
    const int b = blockIdx.z;
    const int h = blockIdx.y;
    const int q = blockIdx.x * 256 + threadIdx.x;

    __shared__ float Ks[64][64];
    __shared__ float Vs[64][64];
    __shared__ float mk[64];

    float qv[DH], o[DH];
    const float* qrow = Qf + ((size_t)(b * SS + q)) * DF + h * DH;
    #pragma unroll
    for (int i = 0; i < DH / 4; i++) {
        float4 v = reinterpret_cast<const float4*>(qrow)[i];
        qv[4*i] = v.x; qv[4*i+1] = v.y; qv[4*i+2] = v.z; qv[4*i+3] = v.w;
    }
    #pragma unroll
    for (int i = 0; i < DH; i++) o[i] = 0.f;

    float m = -1e30f, l = 0.f;

    const int lr = threadIdx.x >> 2;          // 0..63
    const int lc = (threadIdx.x & 3) << 4;    // 0,16,32,48

    for (int kt = 0; kt < SS; kt += 64) {
        __syncthreads();
        const float* kr = Kf + ((size_t)(b * SS + kt + lr)) * DF + h * DH + lc;
        const float* vr = Vf + ((size_t)(b * SS + kt + lr)) * DF + h * DH + lc;
        #pragma unroll
        for (int j = 0; j < 16; j += 4) {
            float4 kv = *reinterpret_cast<const float4*>(kr + j);
            float4 vv = *reinterpret_cast<const float4*>(vr + j);
            *reinterpret_cast<float4*>(&Ks[lr][lc + j]) = kv;
            *reinterpret_cast<float4*>(&Vs[lr][lc + j]) = vv;
        }
        if (threadIdx.x < 64)
            mk[threadIdx.x] = (mask[b * SS + kt + threadIdx.x] == 0) ? 1.f : 0.f;
        __syncthreads();

        for (int k = 0; k < 64; k++) {
            // q . K[k]  (broadcast LDS.128, 4 partial accumulators)
            float d0 = 0.f, d1 = 0.f, d2 = 0.f, d3 = 0.f;
            const float4* krow4 = reinterpret_cast<const float4*>(&Ks[k][0]);
            #pragma unroll
            for (int i = 0; i < 16; i++) {
                float4 kv = krow4[i];
                d0 += qv[4*i]   * kv.x;
                d1 += qv[4*i+1] * kv.y;
                d2 += qv[4*i+2] * kv.z;
                d3 += qv[4*i+3] * kv.w;
            }
            float s = ((d0 + d1) + (d2 + d3)) * 0.03125f;
            if (mk[k] != 0.f) s = -1e9f;

            if (s > m) {                       // deferred rescale (rare)
                float c = __expf(m - s);
                l *= c;
                #pragma unroll
                for (int i = 0; i < DH; i++) o[i] *= c;
                m = s;
            }
            float p = __expf(s - m);
            l += p;

            const float4* vrow4 = reinterpret_cast<const float4*>(&Vs[k][0]);
            #pragma unroll
            for (int i = 0; i < 16; i++) {
                float4 vv = vrow4[i];
                o[4*i]   += p * vv.x;
                o[4*i+1] += p * vv.y;
                o[4*i+2] += p * vv.z;
                o[4*i+3] += p * vv.w;
            }
        }
    }

    float inv = 1.f / l;
    float* xr = Xc + ((size_t)(b * SS + q)) * DF + h * DH;
    #pragma unroll
    for (int i = 0; i < DH / 4; i++) {
        float4 v = {o[4*i] * inv, o[4*i+1] * inv, o[4*i+2] * inv, o[4*i+3] * inv};
        reinterpret_cast<float4*>(xr)[i] = v;
    }
}

// ---------------------------------------------------------------------------
// launch
// ---------------------------------------------------------------------------
extern "C" void kernel_launch(void* const* d_in, const int* in_sizes, int n_in,
                              void* d_out, int out_size)
{
    const float* Q    = (const float*)d_in[0];
    const float* K    = (const float*)d_in[1];
    const float* V    = (const float*)d_in[2];
    const int*   mask = (const int*)  d_in[3];
    const float* Wq   = (const float*)d_in[4];
    const float* bq   = (const float*)d_in[5];
    const float* Wk   = (const float*)d_in[6];
    const float* bk   = (const float*)d_in[7];
    const float* Wv   = (const float*)d_in[8];
    const float* bv   = (const float*)d_in[9];
    const float* Wo   = (const float*)d_in[10];
    const float* bo   = (const float*)d_in[11];
    float* out = (float*)d_out;

    float *Qf, *Kf, *Vf, *Xc;
    cudaGetSymbolAddress((void**)&Qf, g_Qf);
    cudaGetSymbolAddress((void**)&Kf, g_Kf);
    cudaGetSymbolAddress((void**)&Vf, g_Vf);
    cudaGetSymbolAddress((void**)&Xc, g_Xc);

    dim3 ggrid(DF / 64, MROWS / 64);   // (16, 64)
    dim3 gblk(256);

    gemm_nt_bias<<<ggrid, gblk>>>(Q, Wq, bq, Qf);
    gemm_nt_bias<<<ggrid, gblk>>>(K, Wk, bk, Kf);
    gemm_nt_bias<<<ggrid, gblk>>>(V, Wv, bv, Vf);

    attn_kernel<<<dim3(SS / 256, NH, BB), 256>>>(Qf, Kf, Vf, mask, Xc);

    gemm_nt_bias<<<ggrid, gblk>>>(Xc, Wo, bo, out);
}

// round 5
// speedup vs baseline: 1.3031x; 1.3015x over previous
#include <cuda_runtime.h>
#include <cuda_bf16.h>
#include <cstdint>

#define DF 1024
#define NH 16
#define DH 64
#define BB 2
#define SS 2048
#define MROWS (BB*SS)

#define KW   3072              // split-K width (3 * 1024)
#define KC   64                // bf16 K per SMEM chunk
#define NCHUNK (KW / KC)       // 48
#define NSTAGE 3
#define PITCH  72              // bf16 elems per smem row (64 + 8 pad) = 144B
#define PITCHB 144
#define OP_BYTES (128 * PITCHB)             // 18432
#define STAGE_BYTES (2 * OP_BYTES)          // 36864
#define GEMM_SMEM (512 + NSTAGE * STAGE_BYTES)  // 111104

// ---------------------------------------------------------------------------
// Scratch
// ---------------------------------------------------------------------------
__device__ float g_Qf[MROWS * DF];
__device__ float g_Kf[MROWS * DF];
__device__ float g_Vf[MROWS * DF];
__device__ float g_Xc[MROWS * DF];
__device__ __nv_bfloat16 g_A3[(size_t)MROWS * KW];   // activations, split [hi|lo|hi]
__device__ __nv_bfloat16 g_W3[(size_t)DF * KW];      // weights,     split [hi|hi|lo]

// ---------------------------------------------------------------------------
// helpers
// ---------------------------------------------------------------------------
__device__ __forceinline__ uint32_t smem_u32(const void* p) {
    uint32_t a;
    asm("{ .reg .u64 t; cvta.to.shared.u64 t, %1; cvt.u32.u64 %0, t; }"
        : "=r"(a) : "l"(p));
    return a;
}

__device__ __forceinline__ void cp_async_16(uint32_t dst, const void* src) {
    asm volatile("cp.async.cg.shared.global [%0], [%1], 16;" :: "r"(dst), "l"(src) : "memory");
}
#define CP_COMMIT() asm volatile("cp.async.commit_group;" ::: "memory")
#define CP_WAIT1()  asm volatile("cp.async.wait_group 1;" ::: "memory")
#define CP_WAIT0()  asm volatile("cp.async.wait_group 0;" ::: "memory")

__device__ __forceinline__ void ldsm_x4(uint32_t& r0, uint32_t& r1, uint32_t& r2,
                                        uint32_t& r3, uint32_t addr) {
    asm volatile("ldmatrix.sync.aligned.m8n8.x4.shared.b16 {%0,%1,%2,%3}, [%4];"
                 : "=r"(r0), "=r"(r1), "=r"(r2), "=r"(r3) : "r"(addr));
}

__device__ __forceinline__ void mma16816(float* d, const uint32_t* a, const uint32_t* b) {
    asm volatile(
        "mma.sync.aligned.m16n8k16.row.col.f32.bf16.bf16.f32 "
        "{%0,%1,%2,%3}, {%4,%5,%6,%7}, {%8,%9}, {%0,%1,%2,%3};"
        : "+f"(d[0]), "+f"(d[1]), "+f"(d[2]), "+f"(d[3])
        : "r"(a[0]), "r"(a[1]), "r"(a[2]), "r"(a[3]), "r"(b[0]), "r"(b[1]));
}

// ---------------------------------------------------------------------------
// Split-bf16 conversion:
//   mode 0 (activations): Y[r][0:1024]=hi  Y[r][1024:2048]=lo  Y[r][2048:3072]=hi
//   mode 1 (weights):     Y[r][0:1024]=hi  Y[r][1024:2048]=hi  Y[r][2048:3072]=lo
// ---------------------------------------------------------------------------
template<int MODE>
__global__ __launch_bounds__(256) void conv_split(const float* __restrict__ X,
                                                  __nv_bfloat16* __restrict__ Y)
{
    int idx = (blockIdx.x * 256 + threadIdx.x) * 4;
    float4 x = *reinterpret_cast<const float4*>(X + idx);
    float v[4] = {x.x, x.y, x.z, x.w};
    __nv_bfloat16 hi[4], lo[4];
    #pragma unroll
    for (int i = 0; i < 4; i++) {
        hi[i] = __float2bfloat16(v[i]);
        lo[i] = __float2bfloat16(v[i] - __bfloat162float(hi[i]));
    }
    uint64_t hip, lop;
    memcpy(&hip, hi, 8);
    memcpy(&lop, lo, 8);
    int r = idx >> 10, k = idx & 1023;
    size_t base = (size_t)r * KW + k;
    uint64_t* y0 = reinterpret_cast<uint64_t*>(Y + base);
    uint64_t* y1 = reinterpret_cast<uint64_t*>(Y + base + 1024);
    uint64_t* y2 = reinterpret_cast<uint64_t*>(Y + base + 2048);
    *y0 = hip;
    if (MODE == 0) { *y1 = lop; *y2 = hip; }
    else           { *y1 = hip; *y2 = lop; }
}

// ---------------------------------------------------------------------------
// mma.sync GEMM: C[4096,1024] = A3[4096,3072](bf16) @ W3[1024,3072]^T + bias
// 128x128 CTA tile, 8 warps (32x64 warp tiles), KC=64 chunks, 3-stage cp.async.
// ---------------------------------------------------------------------------
__global__ void __launch_bounds__(256, 1)
gemm_mma(const __nv_bfloat16* __restrict__ A3, const __nv_bfloat16* __restrict__ W3,
         const float* __restrict__ bias, float* __restrict__ C)
{
    extern __shared__ char smem[];
    const uint32_t sb = smem_u32(smem);
    const int tid = threadIdx.x;
    const int wid = tid >> 5, lid = tid & 31;
    const int m0 = blockIdx.y * 128;
    const int n0 = blockIdx.x * 128;

    float* bias_s = (float*)smem;
    if (tid < 128) bias_s[tid] = bias[n0 + tid];

    const __nv_bfloat16* Abase = A3 + (size_t)m0 * KW;
    const __nv_bfloat16* Wbase = W3 + (size_t)n0 * KW;

    // chunk loader: 2048 16B segments (A then W), 8 per thread, coalesced rows
    auto load_chunk = [&](int c, int s) {
        const int k0 = c * KC;
        const uint32_t stage = sb + 512 + s * STAGE_BYTES;
        #pragma unroll
        for (int i = 0; i < 8; i++) {
            int seg = i * 256 + tid;
            int op  = seg >> 10;              // 0 = A, 1 = W
            int r   = (seg & 1023) >> 3;      // row 0..127
            int cs  = seg & 7;                // 16B segment within row
            uint32_t dst = stage + op * OP_BYTES + (uint32_t)(r * PITCHB + cs * 16);
            const __nv_bfloat16* src = (op == 0 ? Abase : Wbase)
                                       + (size_t)r * KW + k0 + cs * 8;
            cp_async_16(dst, src);
        }
    };

    // warp tile: 4 warps along M (32 rows each), 2 along N (64 cols each)
    const int m0w = (wid & 3) * 32;
    const int n0w = (wid >> 2) * 64;

    float acc[2][8][4];
    #pragma unroll
    for (int mi = 0; mi < 2; mi++)
        #pragma unroll
        for (int nj = 0; nj < 8; nj++)
            #pragma unroll
            for (int e = 0; e < 4; e++) acc[mi][nj][e] = 0.f;

    // prologue
    load_chunk(0, 0); CP_COMMIT();
    load_chunk(1, 1); CP_COMMIT();

    for (int c = 0; c < NCHUNK; c++) {
        const int s = c % NSTAGE;
        CP_WAIT1();
        __syncthreads();

        int cn = c + 2;
        if (cn < NCHUNK) load_chunk(cn, cn % NSTAGE);
        CP_COMMIT();

        const uint32_t sA = sb + 512 + s * STAGE_BYTES;
        const uint32_t sW = sA + OP_BYTES;

        #pragma unroll
        for (int kk = 0; kk < 4; kk++) {
            uint32_t a[2][4];
            #pragma unroll
            for (int mi = 0; mi < 2; mi++) {
                uint32_t addr = sA + (uint32_t)((m0w + mi * 16 + (lid & 15)) * PITCHB
                                 + kk * 32 + ((lid >> 4) << 4));
                ldsm_x4(a[mi][0], a[mi][1], a[mi][2], a[mi][3], addr);
            }
            uint32_t b[8][2];
            #pragma unroll
            for (int ni = 0; ni < 4; ni++) {
                uint32_t addr = sW + (uint32_t)((n0w + ni * 16 + (lid & 7)
                                 + ((lid >> 4) & 1) * 8) * PITCHB
                                 + kk * 32 + (((lid >> 3) & 1) << 4));
                uint32_t r0, r1, r2, r3;
                ldsm_x4(r0, r1, r2, r3, addr);
                b[2 * ni][0] = r0; b[2 * ni][1] = r1;
                b[2 * ni + 1][0] = r2; b[2 * ni + 1][1] = r3;
            }
            #pragma unroll
            for (int mi = 0; mi < 2; mi++)
                #pragma unroll
                for (int nj = 0; nj < 8; nj++)
                    mma16816(acc[mi][nj], a[mi], b[nj]);
        }
        __syncthreads();
    }
    CP_WAIT0();

    // epilogue: direct STG from c-frag layout, +bias
    const int g = lid >> 2, t = lid & 3;
    #pragma unroll
    for (int mi = 0; mi < 2; mi++) {
        #pragma unroll
        for (int nj = 0; nj < 8; nj++) {
            int colrel = n0w + nj * 8 + 2 * t;
            int col = n0 + colrel;
            int row0 = m0 + m0w + mi * 16 + g;
            float2 v0 = {acc[mi][nj][0] + bias_s[colrel],
                         acc[mi][nj][1] + bias_s[colrel + 1]};
            float2 v1 = {acc[mi][nj][2] + bias_s[colrel],
                         acc[mi][nj][3] + bias_s[colrel + 1]};
            *reinterpret_cast<float2*>(C + (size_t)row0 * DF + col) = v0;
            *reinterpret_cast<float2*>(C + (size_t)(row0 + 8) * DF + col) = v1;
        }
    }
}

// ---------------------------------------------------------------------------
// Flash-style attention (unchanged)
// ---------------------------------------------------------------------------
__global__ __launch_bounds__(256) void attn_kernel(
    const float* __restrict__ Qf, const float* __restrict__ Kf,
    const float* __restrict__ Vf, const int* __restrict__ mask,
    float* __restrict__ Xc)
{
    const int b = blockIdx.z;
    const int h = blockIdx.y;
    const int q = blockIdx.x * 256 + threadIdx.x;

    __shared__ float Ks[64][64];
    __shared__ float Vs[64][64];
    __shared__ float mk[64];

    float qv[DH], o[DH];
    const float* qrow = Qf + ((size_t)(b * SS + q)) * DF + h * DH;
    #pragma unroll
    for (int i = 0; i < DH / 4; i++) {
        float4 v = reinterpret_cast<const float4*>(qrow)[i];
        qv[4*i] = v.x; qv[4*i+1] = v.y; qv[4*i+2] = v.z; qv[4*i+3] = v.w;
    }
    #pragma unroll
    for (int i = 0; i < DH; i++) o[i] = 0.f;

    float m = -1e30f, l = 0.f;

    const int lr = threadIdx.x >> 2;
    const int lc = (threadIdx.x & 3) << 4;

    for (int kt = 0; kt < SS; kt += 64) {
        __syncthreads();
        const float* kr = Kf + ((size_t)(b * SS + kt + lr)) * DF + h * DH + lc;
        const float* vr = Vf + ((size_t)(b * SS + kt + lr)) * DF + h * DH + lc;
        #pragma unroll
        for (int j = 0; j < 16; j += 4) {
            float4 kv = *reinterpret_cast<const float4*>(kr + j);
            float4 vv = *reinterpret_cast<const float4*>(vr + j);
            *reinterpret_cast<float4*>(&Ks[lr][lc + j]) = kv;
            *reinterpret_cast<float4*>(&Vs[lr][lc + j]) = vv;
        }
        if (threadIdx.x < 64)
            mk[threadIdx.x] = (mask[b * SS + kt + threadIdx.x] == 0) ? 1.f : 0.f;
        __syncthreads();

        for (int k = 0; k < 64; k++) {
            float d0 = 0.f, d1 = 0.f, d2 = 0.f, d3 = 0.f;
            const float4* krow4 = reinterpret_cast<const float4*>(&Ks[k][0]);
            #pragma unroll
            for (int i = 0; i < 16; i++) {
                float4 kv = krow4[i];
                d0 += qv[4*i]   * kv.x;
                d1 += qv[4*i+1] * kv.y;
                d2 += qv[4*i+2] * kv.z;
                d3 += qv[4*i+3] * kv.w;
            }
            float s = ((d0 + d1) + (d2 + d3)) * 0.03125f;
            if (mk[k] != 0.f) s = -1e9f;

            if (s > m) {
                float c = __expf(m - s);
                l *= c;
                #pragma unroll
                for (int i = 0; i < DH; i++) o[i] *= c;
                m = s;
            }
            float p = __expf(s - m);
            l += p;

            const float4* vrow4 = reinterpret_cast<const float4*>(&Vs[k][0]);
            #pragma unroll
            for (int i = 0; i < 16; i++) {
                float4 vv = vrow4[i];
                o[4*i]   += p * vv.x;
                o[4*i+1] += p * vv.y;
                o[4*i+2] += p * vv.z;
                o[4*i+3] += p * vv.w;
            }
        }
    }

    float inv = 1.f / l;
    float* xr = Xc + ((size_t)(b * SS + q)) * DF + h * DH;
    #pragma unroll
    for (int i = 0; i < DH / 4; i++) {
        float4 v = {o[4*i] * inv, o[4*i+1] * inv, o[4*i+2] * inv, o[4*i+3] * inv};
        reinterpret_cast<float4*>(xr)[i] = v;
    }
}

// ---------------------------------------------------------------------------
// launch
// ---------------------------------------------------------------------------
extern "C" void kernel_launch(void* const* d_in, const int* in_sizes, int n_in,
                              void* d_out, int out_size)
{
    const float* Q    = (const float*)d_in[0];
    const float* K    = (const float*)d_in[1];
    const float* V    = (const float*)d_in[2];
    const int*   mask = (const int*)  d_in[3];
    const float* Wq   = (const float*)d_in[4];
    const float* bq   = (const float*)d_in[5];
    const float* Wk   = (const float*)d_in[6];
    const float* bk   = (const float*)d_in[7];
    const float* Wv   = (const float*)d_in[8];
    const float* bv   = (const float*)d_in[9];
    const float* Wo   = (const float*)d_in[10];
    const float* bo   = (const float*)d_in[11];
    float* out = (float*)d_out;

    float *Qf, *Kf, *Vf, *Xc;
    __nv_bfloat16 *A3, *W3;
    cudaGetSymbolAddress((void**)&Qf, g_Qf);
    cudaGetSymbolAddress((void**)&Kf, g_Kf);
    cudaGetSymbolAddress((void**)&Vf, g_Vf);
    cudaGetSymbolAddress((void**)&Xc, g_Xc);
    cudaGetSymbolAddress((void**)&A3, g_A3);
    cudaGetSymbolAddress((void**)&W3, g_W3);

    cudaFuncSetAttribute(gemm_mma, cudaFuncAttributeMaxDynamicSharedMemorySize, GEMM_SMEM);

    const dim3 ggrid(DF / 128, MROWS / 128);   // (8, 32)
    const int convA_blocks = MROWS * DF / (256 * 4);   // 4096
    const int convW_blocks = DF * DF / (256 * 4);      // 1024

    // Q projection
    conv_split<1><<<convW_blocks, 256>>>(Wq, W3);
    conv_split<0><<<convA_blocks, 256>>>(Q, A3);
    gemm_mma<<<ggrid, 256, GEMM_SMEM>>>(A3, W3, bq, Qf);
    // K projection
    conv_split<1><<<convW_blocks, 256>>>(Wk, W3);
    conv_split<0><<<convA_blocks, 256>>>(K, A3);
    gemm_mma<<<ggrid, 256, GEMM_SMEM>>>(A3, W3, bk, Kf);
    // V projection
    conv_split<1><<<convW_blocks, 256>>>(Wv, W3);
    conv_split<0><<<convA_blocks, 256>>>(V, A3);
    gemm_mma<<<ggrid, 256, GEMM_SMEM>>>(A3, W3, bv, Vf);

    attn_kernel<<<dim3(SS / 256, NH, BB), 256>>>(Qf, Kf, Vf, mask, Xc);

    // output projection
    conv_split<1><<<convW_blocks, 256>>>(Wo, W3);
    conv_split<0><<<convA_blocks, 256>>>(Xc, A3);
    gemm_mma<<<ggrid, 256, GEMM_SMEM>>>(A3, W3, bo, out);
}

// round 6
// speedup vs baseline: 2.9165x; 2.2382x over previous
#include <cuda_runtime.h>
#include <cuda_bf16.h>
#include <cstdint>

#define DF 1024
#define NH 16
#define DH 64
#define BB 2
#define SS 2048
#define MROWS (BB*SS)

#define KW   3072              // split-K width (3 * 1024)
#define KC   64                // bf16 K per SMEM chunk
#define NCHUNK (KW / KC)       // 48
#define NSTAGE 3
#define PITCH  72              // bf16 elems per smem row (64 + 8 pad) = 144B
#define PITCHB 144
#define OP_BYTES (128 * PITCHB)             // 18432
#define STAGE_BYTES (2 * OP_BYTES)          // 36864
#define GEMM_SMEM (512 + NSTAGE * STAGE_BYTES)  // 111104

// attention smem
#define ATILE   9216                       // one 64x64 bf16 tile, pitch 144
#define ASTRIDE (4 * ATILE + 256)          // Kh,Kl,Vh,Vl + mask = 37120
#define QL_OFF  18432
#define ATTN_SMEM (3 * ASTRIDE)            // 111360

// ---------------------------------------------------------------------------
// Scratch
// ---------------------------------------------------------------------------
__device__ __nv_bfloat16 g_A3[(size_t)MROWS * KW];   // activations, split [hi|lo|hi]
__device__ __nv_bfloat16 g_W3[(size_t)DF * KW];      // weights,     split [hi|hi|lo]
__device__ __nv_bfloat16 g_Qh[(size_t)BB * NH * SS * DH];
__device__ __nv_bfloat16 g_Ql[(size_t)BB * NH * SS * DH];
__device__ __nv_bfloat16 g_Kh[(size_t)BB * NH * SS * DH];
__device__ __nv_bfloat16 g_Kl[(size_t)BB * NH * SS * DH];
__device__ __nv_bfloat16 g_Vh[(size_t)BB * NH * SS * DH];
__device__ __nv_bfloat16 g_Vl[(size_t)BB * NH * SS * DH];

// ---------------------------------------------------------------------------
// helpers
// ---------------------------------------------------------------------------
__device__ __forceinline__ uint32_t smem_u32(const void* p) {
    uint32_t a;
    asm("{ .reg .u64 t; cvta.to.shared.u64 t, %1; cvt.u32.u64 %0, t; }"
        : "=r"(a) : "l"(p));
    return a;
}

__device__ __forceinline__ void cp_async_16(uint32_t dst, const void* src) {
    asm volatile("cp.async.cg.shared.global [%0], [%1], 16;" :: "r"(dst), "l"(src) : "memory");
}
#define CP_COMMIT() asm volatile("cp.async.commit_group;" ::: "memory")
#define CP_WAIT1()  asm volatile("cp.async.wait_group 1;" ::: "memory")
#define CP_WAIT0()  asm volatile("cp.async.wait_group 0;" ::: "memory")

__device__ __forceinline__ void ldsm_x4(uint32_t& r0, uint32_t& r1, uint32_t& r2,
                                        uint32_t& r3, uint32_t addr) {
    asm volatile("ldmatrix.sync.aligned.m8n8.x4.shared.b16 {%0,%1,%2,%3}, [%4];"
                 : "=r"(r0), "=r"(r1), "=r"(r2), "=r"(r3) : "r"(addr));
}
__device__ __forceinline__ void ldsm_x4_t(uint32_t& r0, uint32_t& r1, uint32_t& r2,
                                          uint32_t& r3, uint32_t addr) {
    asm volatile("ldmatrix.sync.aligned.m8n8.x4.trans.shared.b16 {%0,%1,%2,%3}, [%4];"
                 : "=r"(r0), "=r"(r1), "=r"(r2), "=r"(r3) : "r"(addr));
}

__device__ __forceinline__ void mma16816(float* d, const uint32_t* a, const uint32_t* b) {
    asm volatile(
        "mma.sync.aligned.m16n8k16.row.col.f32.bf16.bf16.f32 "
        "{%0,%1,%2,%3}, {%4,%5,%6,%7}, {%8,%9}, {%0,%1,%2,%3};"
        : "+f"(d[0]), "+f"(d[1]), "+f"(d[2]), "+f"(d[3])
        : "r"(a[0]), "r"(a[1]), "r"(a[2]), "r"(a[3]), "r"(b[0]), "r"(b[1]));
}

// truncation hi-split + rounded lo-split of a float pair into two bf16x2 words
__device__ __forceinline__ void split_pack(float x, float y, uint32_t& hp, uint32_t& lp) {
    uint32_t ux = __float_as_uint(x), uy = __float_as_uint(y);
    hp = __byte_perm(ux, uy, 0x7632);
    float lx = x - __uint_as_float(ux & 0xffff0000u);
    float ly = y - __uint_as_float(uy & 0xffff0000u);
    __nv_bfloat162 l2 = __floats2bfloat162_rn(lx, ly);
    lp = *reinterpret_cast<uint32_t*>(&l2);
}

// ---------------------------------------------------------------------------
// Split-bf16 conversion (inputs -> A3 / weights -> W3)
//   mode 0 (activations): [0:1024]=hi  [1024:2048]=lo  [2048:3072]=hi
//   mode 1 (weights):     [0:1024]=hi  [1024:2048]=hi  [2048:3072]=lo
// ---------------------------------------------------------------------------
template<int MODE>
__global__ __launch_bounds__(256) void conv_split(const float* __restrict__ X,
                                                  __nv_bfloat16* __restrict__ Y)
{
    int idx = (blockIdx.x * 256 + threadIdx.x) * 4;
    float4 x = *reinterpret_cast<const float4*>(X + idx);
    float v[4] = {x.x, x.y, x.z, x.w};
    __nv_bfloat16 hi[4], lo[4];
    #pragma unroll
    for (int i = 0; i < 4; i++) {
        hi[i] = __float2bfloat16(v[i]);
        lo[i] = __float2bfloat16(v[i] - __bfloat162float(hi[i]));
    }
    uint64_t hip, lop;
    memcpy(&hip, hi, 8);
    memcpy(&lop, lo, 8);
    int r = idx >> 10, k = idx & 1023;
    size_t base = (size_t)r * KW + k;
    uint64_t* y0 = reinterpret_cast<uint64_t*>(Y + base);
    uint64_t* y1 = reinterpret_cast<uint64_t*>(Y + base + 1024);
    uint64_t* y2 = reinterpret_cast<uint64_t*>(Y + base + 2048);
    *y0 = hip;
    if (MODE == 0) { *y1 = lop; *y2 = hip; }
    else           { *y1 = hip; *y2 = lop; }
}

// ---------------------------------------------------------------------------
// mma.sync GEMM: C[4096,1024] = A3 @ W3^T + bias
// EPI=0: write fp32 to C.   EPI=1: write split bf16 head-major to (H, L).
// ---------------------------------------------------------------------------
template<int EPI>
__global__ void __launch_bounds__(256, 1)
gemm_mma(const __nv_bfloat16* __restrict__ A3, const __nv_bfloat16* __restrict__ W3,
         const float* __restrict__ bias, float* __restrict__ C,
         __nv_bfloat16* __restrict__ H, __nv_bfloat16* __restrict__ L)
{
    extern __shared__ char smem[];
    const uint32_t sb = smem_u32(smem);
    const int tid = threadIdx.x;
    const int wid = tid >> 5, lid = tid & 31;
    const int m0 = blockIdx.y * 128;
    const int n0 = blockIdx.x * 128;

    float* bias_s = (float*)smem;
    if (tid < 128) bias_s[tid] = bias[n0 + tid];

    const __nv_bfloat16* Abase = A3 + (size_t)m0 * KW;
    const __nv_bfloat16* Wbase = W3 + (size_t)n0 * KW;

    auto load_chunk = [&](int c, int s) {
        const int k0 = c * KC;
        const uint32_t stage = sb + 512 + s * STAGE_BYTES;
        #pragma unroll
        for (int i = 0; i < 8; i++) {
            int seg = i * 256 + tid;
            int op  = seg >> 10;
            int r   = (seg & 1023) >> 3;
            int cs  = seg & 7;
            uint32_t dst = stage + op * OP_BYTES + (uint32_t)(r * PITCHB + cs * 16);
            const __nv_bfloat16* src = (op == 0 ? Abase : Wbase)
                                       + (size_t)r * KW + k0 + cs * 8;
            cp_async_16(dst, src);
        }
    };

    const int m0w = (wid & 3) * 32;
    const int n0w = (wid >> 2) * 64;

    float acc[2][8][4];
    #pragma unroll
    for (int mi = 0; mi < 2; mi++)
        #pragma unroll
        for (int nj = 0; nj < 8; nj++)
            #pragma unroll
            for (int e = 0; e < 4; e++) acc[mi][nj][e] = 0.f;

    load_chunk(0, 0); CP_COMMIT();
    load_chunk(1, 1); CP_COMMIT();

    for (int c = 0; c < NCHUNK; c++) {
        const int s = c % NSTAGE;
        CP_WAIT1();
        __syncthreads();

        int cn = c + 2;
        if (cn < NCHUNK) load_chunk(cn, cn % NSTAGE);
        CP_COMMIT();

        const uint32_t sA = sb + 512 + s * STAGE_BYTES;
        const uint32_t sW = sA + OP_BYTES;

        #pragma unroll
        for (int kk = 0; kk < 4; kk++) {
            uint32_t a[2][4];
            #pragma unroll
            for (int mi = 0; mi < 2; mi++) {
                uint32_t addr = sA + (uint32_t)((m0w + mi * 16 + (lid & 15)) * PITCHB
                                 + kk * 32 + ((lid >> 4) << 4));
                ldsm_x4(a[mi][0], a[mi][1], a[mi][2], a[mi][3], addr);
            }
            uint32_t b[8][2];
            #pragma unroll
            for (int ni = 0; ni < 4; ni++) {
                uint32_t addr = sW + (uint32_t)((n0w + ni * 16 + (lid & 7)
                                 + ((lid >> 4) & 1) * 8) * PITCHB
                                 + kk * 32 + (((lid >> 3) & 1) << 4));
                uint32_t r0, r1, r2, r3;
                ldsm_x4(r0, r1, r2, r3, addr);
                b[2 * ni][0] = r0; b[2 * ni][1] = r1;
                b[2 * ni + 1][0] = r2; b[2 * ni + 1][1] = r3;
            }
            #pragma unroll
            for (int mi = 0; mi < 2; mi++)
                #pragma unroll
                for (int nj = 0; nj < 8; nj++)
                    mma16816(acc[mi][nj], a[mi], b[nj]);
        }
        __syncthreads();
    }
    CP_WAIT0();

    const int g = lid >> 2, t = lid & 3;
    #pragma unroll
    for (int mi = 0; mi < 2; mi++) {
        #pragma unroll
        for (int nj = 0; nj < 8; nj++) {
            int colrel = n0w + nj * 8 + 2 * t;
            int col = n0 + colrel;
            int row0 = m0 + m0w + mi * 16 + g;
            float c0 = acc[mi][nj][0] + bias_s[colrel];
            float c1 = acc[mi][nj][1] + bias_s[colrel + 1];
            float c2 = acc[mi][nj][2] + bias_s[colrel];
            float c3 = acc[mi][nj][3] + bias_s[colrel + 1];
            if (EPI == 0) {
                float2 v0 = {c0, c1}, v1 = {c2, c3};
                *reinterpret_cast<float2*>(C + (size_t)row0 * DF + col) = v0;
                *reinterpret_cast<float2*>(C + (size_t)(row0 + 8) * DF + col) = v1;
            } else {
                int bb_ = row0 >> 11, sidx = row0 & 2047;
                int hh  = col >> 6,   dh   = col & 63;
                size_t dst = ((size_t)(bb_ * NH + hh) * SS + sidx) * DH + dh;
                uint32_t hp, lp;
                split_pack(c0, c1, hp, lp);
                *reinterpret_cast<uint32_t*>(H + dst) = hp;
                *reinterpret_cast<uint32_t*>(L + dst) = lp;
                split_pack(c2, c3, hp, lp);
                *reinterpret_cast<uint32_t*>(H + dst + 8 * DH) = hp;
                *reinterpret_cast<uint32_t*>(L + dst + 8 * DH) = lp;
            }
        }
    }
}

// ---------------------------------------------------------------------------
// FlashAttention-2 on mma.sync, 3-term bf16 split for QK^T and PV.
// CTA: 128 queries x one (b,h). 8 warps x 16 rows. 64-key tiles, 3-stage pipe.
// Writes normalized output directly into A3 split layout [hi|lo|hi].
// ---------------------------------------------------------------------------
__global__ void __launch_bounds__(256, 1)
attn_mma(const __nv_bfloat16* __restrict__ Qh_, const __nv_bfloat16* __restrict__ Ql_,
         const __nv_bfloat16* __restrict__ Kh_, const __nv_bfloat16* __restrict__ Kl_,
         const __nv_bfloat16* __restrict__ Vh_, const __nv_bfloat16* __restrict__ Vl_,
         const int* __restrict__ mask, __nv_bfloat16* __restrict__ A3out)
{
    extern __shared__ char smem[];
    const uint32_t sb = smem_u32(smem);
    const int tid = threadIdx.x, wid = tid >> 5, lid = tid & 31;
    const int g = lid >> 2, t4 = lid & 3;
    const int b = blockIdx.z, h = blockIdx.y;
    const int bh = b * NH + h;
    const int q0 = blockIdx.x * 128;
    const int m0w = wid * 16;
    const float SC = 0.03125f;   // 1/sqrt(D_FEAT) = 1/32

    // ---- stage Q (hi,lo) through smem into register a-frags ----
    {
        const size_t qbase = ((size_t)bh * SS + q0);
        #pragma unroll
        for (int i = 0; i < 4; i++) {
            int seg = i * 256 + tid;             // 0..1023
            int row = seg >> 3, cs = seg & 7;
            const size_t src = (qbase + row) * DH + cs * 8;
            uint32_t d = sb + (uint32_t)(row * PITCHB + cs * 16);
            cp_async_16(d,          Qh_ + src);
            cp_async_16(d + QL_OFF, Ql_ + src);
        }
    }
    CP_COMMIT(); CP_WAIT0(); __syncthreads();

    uint32_t qh[4][4], ql[4][4];
    #pragma unroll
    for (int kk = 0; kk < 4; kk++) {
        uint32_t a = sb + (uint32_t)((m0w + (lid & 15)) * PITCHB + kk * 32 + ((lid >> 4) << 4));
        ldsm_x4(qh[kk][0], qh[kk][1], qh[kk][2], qh[kk][3], a);
        ldsm_x4(ql[kk][0], ql[kk][1], ql[kk][2], ql[kk][3], a + QL_OFF);
    }
    __syncthreads();

    auto load_tile = [&](int ti, int st) {
        const uint32_t stage = sb + st * ASTRIDE;
        const size_t kbase = ((size_t)bh * SS + ti * 64);
        #pragma unroll
        for (int i = 0; i < 2; i++) {
            int seg = i * 256 + tid;             // 0..511
            int row = seg >> 3, cs = seg & 7;
            size_t src = (kbase + row) * DH + cs * 8;
            uint32_t d = stage + (uint32_t)(row * PITCHB + cs * 16);
            cp_async_16(d,             Kh_ + src);
            cp_async_16(d + ATILE,     Kl_ + src);
            cp_async_16(d + 2 * ATILE, Vh_ + src);
            cp_async_16(d + 3 * ATILE, Vl_ + src);
        }
        if (tid < 16)
            cp_async_16(stage + 4 * ATILE + tid * 16, mask + b * SS + ti * 64 + tid * 4);
    };

    float m0 = -1e30f, m1 = -1e30f, l0 = 0.f, l1 = 0.f;
    float o[8][4];
    #pragma unroll
    for (int nj = 0; nj < 8; nj++)
        #pragma unroll
        for (int e = 0; e < 4; e++) o[nj][e] = 0.f;

    load_tile(0, 0); CP_COMMIT();
    load_tile(1, 1); CP_COMMIT();

    for (int ti = 0; ti < SS / 64; ti++) {
        const int st = ti % 3;
        CP_WAIT1();
        __syncthreads();
        if (ti + 2 < SS / 64) load_tile(ti + 2, (ti + 2) % 3);
        CP_COMMIT();

        const uint32_t sK  = sb + st * ASTRIDE;
        const uint32_t sKl = sK + ATILE, sV = sK + 2 * ATILE, sVl = sK + 3 * ATILE;
        const int* mk = (const int*)(smem + st * ASTRIDE + 4 * ATILE);

        // ---- S = Qh Kh^T + Ql Kh^T + Qh Kl^T ----
        float s[8][4];
        #pragma unroll
        for (int nj = 0; nj < 8; nj++)
            #pragma unroll
            for (int e = 0; e < 4; e++) s[nj][e] = 0.f;

        #pragma unroll
        for (int kk = 0; kk < 4; kk++) {
            uint32_t kb[4][4];
            #pragma unroll
            for (int ni = 0; ni < 4; ni++) {
                uint32_t a = sK + (uint32_t)((ni * 16 + (lid & 7) + ((lid >> 4) & 1) * 8) * PITCHB
                             + kk * 32 + (((lid >> 3) & 1) << 4));
                ldsm_x4(kb[ni][0], kb[ni][1], kb[ni][2], kb[ni][3], a);
            }
            #pragma unroll
            for (int nj = 0; nj < 8; nj++) mma16816(s[nj], qh[kk], &kb[nj >> 1][(nj & 1) * 2]);
            #pragma unroll
            for (int nj = 0; nj < 8; nj++) mma16816(s[nj], ql[kk], &kb[nj >> 1][(nj & 1) * 2]);
            #pragma unroll
            for (int ni = 0; ni < 4; ni++) {
                uint32_t a = sKl + (uint32_t)((ni * 16 + (lid & 7) + ((lid >> 4) & 1) * 8) * PITCHB
                             + kk * 32 + (((lid >> 3) & 1) << 4));
                ldsm_x4(kb[ni][0], kb[ni][1], kb[ni][2], kb[ni][3], a);
            }
            #pragma unroll
            for (int nj = 0; nj < 8; nj++) mma16816(s[nj], qh[kk], &kb[nj >> 1][(nj & 1) * 2]);
        }

        // ---- scale + mask + online softmax ----
        float tmax0 = -1e30f, tmax1 = -1e30f;
        #pragma unroll
        for (int nj = 0; nj < 8; nj++) {
            int c0 = nj * 8 + 2 * t4;
            int mk0 = mk[c0], mk1 = mk[c0 + 1];
            float s0 = s[nj][0] * SC; if (mk0 == 0) s0 = -1e9f;
            float s1 = s[nj][1] * SC; if (mk1 == 0) s1 = -1e9f;
            float s2 = s[nj][2] * SC; if (mk0 == 0) s2 = -1e9f;
            float s3 = s[nj][3] * SC; if (mk1 == 0) s3 = -1e9f;
            s[nj][0] = s0; s[nj][1] = s1; s[nj][2] = s2; s[nj][3] = s3;
            tmax0 = fmaxf(tmax0, fmaxf(s0, s1));
            tmax1 = fmaxf(tmax1, fmaxf(s2, s3));
        }
        tmax0 = fmaxf(tmax0, __shfl_xor_sync(0xffffffffu, tmax0, 1));
        tmax0 = fmaxf(tmax0, __shfl_xor_sync(0xffffffffu, tmax0, 2));
        tmax1 = fmaxf(tmax1, __shfl_xor_sync(0xffffffffu, tmax1, 1));
        tmax1 = fmaxf(tmax1, __shfl_xor_sync(0xffffffffu, tmax1, 2));

        float mn0 = fmaxf(m0, tmax0), mn1 = fmaxf(m1, tmax1);
        float sc0 = __expf(m0 - mn0), sc1 = __expf(m1 - mn1);
        m0 = mn0; m1 = mn1;
        l0 *= sc0; l1 *= sc1;
        #pragma unroll
        for (int nj = 0; nj < 8; nj++) {
            o[nj][0] *= sc0; o[nj][1] *= sc0;
            o[nj][2] *= sc1; o[nj][3] *= sc1;
        }
        #pragma unroll
        for (int nj = 0; nj < 8; nj++) {
            float p0 = __expf(s[nj][0] - m0);
            float p1 = __expf(s[nj][1] - m0);
            float p2 = __expf(s[nj][2] - m1);
            float p3 = __expf(s[nj][3] - m1);
            s[nj][0] = p0; s[nj][1] = p1; s[nj][2] = p2; s[nj][3] = p3;
            l0 += p0 + p1; l1 += p2 + p3;
        }

        // ---- O += Ph Vh + Pl Vh + Ph Vl ----
        #pragma unroll
        for (int kk = 0; kk < 4; kk++) {
            uint32_t ah[4], al[4];
            split_pack(s[2 * kk][0],     s[2 * kk][1],     ah[0], al[0]);
            split_pack(s[2 * kk][2],     s[2 * kk][3],     ah[1], al[1]);
            split_pack(s[2 * kk + 1][0], s[2 * kk + 1][1], ah[2], al[2]);
            split_pack(s[2 * kk + 1][2], s[2 * kk + 1][3], ah[3], al[3]);

            uint32_t vb[4][4];
            #pragma unroll
            for (int njp = 0; njp < 4; njp++) {
                uint32_t a = sV + (uint32_t)((16 * kk + (lid & 7) + ((lid >> 3) & 1) * 8) * PITCHB
                             + (16 * njp + ((lid >> 4) & 1) * 8) * 2);
                ldsm_x4_t(vb[njp][0], vb[njp][1], vb[njp][2], vb[njp][3], a);
            }
            #pragma unroll
            for (int nj = 0; nj < 8; nj++) mma16816(o[nj], ah, &vb[nj >> 1][(nj & 1) * 2]);
            #pragma unroll
            for (int nj = 0; nj < 8; nj++) mma16816(o[nj], al, &vb[nj >> 1][(nj & 1) * 2]);
            #pragma unroll
            for (int njp = 0; njp < 4; njp++) {
                uint32_t a = sVl + (uint32_t)((16 * kk + (lid & 7) + ((lid >> 3) & 1) * 8) * PITCHB
                             + (16 * njp + ((lid >> 4) & 1) * 8) * 2);
                ldsm_x4_t(vb[njp][0], vb[njp][1], vb[njp][2], vb[njp][3], a);
            }
            #pragma unroll
            for (int nj = 0; nj < 8; nj++) mma16816(o[nj], ah, &vb[nj >> 1][(nj & 1) * 2]);
        }
        __syncthreads();
    }
    CP_WAIT0();

    // ---- finalize + write split bf16 straight into A3 [hi|lo|hi] ----
    l0 += __shfl_xor_sync(0xffffffffu, l0, 1);
    l0 += __shfl_xor_sync(0xffffffffu, l0, 2);
    l1 += __shfl_xor_sync(0xffffffffu, l1, 1);
    l1 += __shfl_xor_sync(0xffffffffu, l1, 2);
    float inv0 = 1.f / l0, inv1 = 1.f / l1;

    const int srow = q0 + m0w + g;
    size_t r0 = (size_t)(b * SS + srow) * KW;
    size_t r1 = r0 + (size_t)8 * KW;
    const int colbase = h * DH;

    #pragma unroll
    for (int nj = 0; nj < 8; nj++) {
        int c = colbase + nj * 8 + 2 * t4;
        uint32_t hp, lp;
        split_pack(o[nj][0] * inv0, o[nj][1] * inv0, hp, lp);
        *reinterpret_cast<uint32_t*>(A3out + r0 + c)        = hp;
        *reinterpret_cast<uint32_t*>(A3out + r0 + 1024 + c) = lp;
        *reinterpret_cast<uint32_t*>(A3out + r0 + 2048 + c) = hp;
        split_pack(o[nj][2] * inv1, o[nj][3] * inv1, hp, lp);
        *reinterpret_cast<uint32_t*>(A3out + r1 + c)        = hp;
        *reinterpret_cast<uint32_t*>(A3out + r1 + 1024 + c) = lp;
        *reinterpret_cast<uint32_t*>(A3out + r1 + 2048 + c) = hp;
    }
}

// ---------------------------------------------------------------------------
// launch
// ---------------------------------------------------------------------------
extern "C" void kernel_launch(void* const* d_in, const int* in_sizes, int n_in,
                              void* d_out, int out_size)
{
    const float* Q    = (const float*)d_in[0];
    const float* K    = (const float*)d_in[1];
    const float* V    = (const float*)d_in[2];
    const int*   mask = (const int*)  d_in[3];
    const float* Wq   = (const float*)d_in[4];
    const float* bq   = (const float*)d_in[5];
    const float* Wk   = (const float*)d_in[6];
    const float* bk   = (const float*)d_in[7];
    const float* Wv   = (const float*)d_in[8];
    const float* bv   = (const float*)d_in[9];
    const float* Wo   = (const float*)d_in[10];
    const float* bo   = (const float*)d_in[11];
    float* out = (float*)d_out;

    __nv_bfloat16 *A3, *W3, *Qh, *Ql, *Kh, *Kl, *Vh, *Vl;
    cudaGetSymbolAddress((void**)&A3, g_A3);
    cudaGetSymbolAddress((void**)&W3, g_W3);
    cudaGetSymbolAddress((void**)&Qh, g_Qh);
    cudaGetSymbolAddress((void**)&Ql, g_Ql);
    cudaGetSymbolAddress((void**)&Kh, g_Kh);
    cudaGetSymbolAddress((void**)&Kl, g_Kl);
    cudaGetSymbolAddress((void**)&Vh, g_Vh);
    cudaGetSymbolAddress((void**)&Vl, g_Vl);

    cudaFuncSetAttribute(gemm_mma<0>, cudaFuncAttributeMaxDynamicSharedMemorySize, GEMM_SMEM);
    cudaFuncSetAttribute(gemm_mma<1>, cudaFuncAttributeMaxDynamicSharedMemorySize, GEMM_SMEM);
    cudaFuncSetAttribute(attn_mma,    cudaFuncAttributeMaxDynamicSharedMemorySize, ATTN_SMEM);

    const dim3 ggrid(DF / 128, MROWS / 128);           // (8, 32)
    const int convA_blocks = MROWS * DF / (256 * 4);   // 4096
    const int convW_blocks = DF * DF / (256 * 4);      // 1024

    // Q projection -> split bf16 head-major
    conv_split<1><<<convW_blocks, 256>>>(Wq, W3);
    conv_split<0><<<convA_blocks, 256>>>(Q, A3);
    gemm_mma<1><<<ggrid, 256, GEMM_SMEM>>>(A3, W3, bq, nullptr, Qh, Ql);
    // K projection
    conv_split<1><<<convW_blocks, 256>>>(Wk, W3);
    conv_split<0><<<convA_blocks, 256>>>(K, A3);
    gemm_mma<1><<<ggrid, 256, GEMM_SMEM>>>(A3, W3, bk, nullptr, Kh, Kl);
    // V projection
    conv_split<1><<<convW_blocks, 256>>>(Wv, W3);
    conv_split<0><<<convA_blocks, 256>>>(V, A3);
    gemm_mma<1><<<ggrid, 256, GEMM_SMEM>>>(A3, W3, bv, nullptr, Vh, Vl);

    // attention -> writes A3 directly (split [hi|lo|hi])
    attn_mma<<<dim3(SS / 128, NH, BB), 256, ATTN_SMEM>>>(Qh, Ql, Kh, Kl, Vh, Vl, mask, A3);

    // output projection
    conv_split<1><<<convW_blocks, 256>>>(Wo, W3);
    gemm_mma<0><<<ggrid, 256, GEMM_SMEM>>>(A3, W3, bo, out, nullptr, nullptr);
}